// round 3
// baseline (speedup 1.0000x reference)
#include <cuda_runtime.h>
#include <math.h>

// Problem constants (fixed by the reference)
#define VOCAB  100000
#define DIM    128
#define BATCH  4096
#define CTX    10
#define NNEG   200   // CTX * N_NEGS
#define FULL   0xffffffffu

__device__ __forceinline__ float log_sigmoid(float x) {
    // log(sigmoid(x)) = min(x,0) - log(1 + exp(-|x|)); arg of log in (1,2] -> __logf ok
    float ax = fabsf(x);
    return fminf(x, 0.0f) - __logf(1.0f + __expf(-ax));
}

__device__ __forceinline__ float dot4(const float4 a, const float4 b) {
    return fmaf(a.x, b.x, fmaf(a.y, b.y, fmaf(a.z, b.z, a.w * b.w)));
}

// Merge two per-lane partial-sum sets across the `bit` butterfly.
__device__ __forceinline__ float merge2(float a, float b, int lane, int bit) {
    float send = (lane & bit) ? a : b;
    float recv = __shfl_xor_sync(FULL, send, bit);
    float keep = (lane & bit) ? b : a;
    return keep + recv;
}

// Reduce 8 independent per-lane partial sums; each row's full sum lands in 4 lanes.
__device__ __forceinline__ float reduce8(const float p[8], int lane) {
    float m0 = merge2(p[0], p[1], lane, 16);
    float m1 = merge2(p[2], p[3], lane, 16);
    float m2 = merge2(p[4], p[5], lane, 16);
    float m3 = merge2(p[6], p[7], lane, 16);
    float n0 = merge2(m0, m1, lane, 8);
    float n1 = merge2(m2, m3, lane, 8);
    float r  = merge2(n0, n1, lane, 4);
    r += __shfl_xor_sync(FULL, r, 2);
    r += __shfl_xor_sync(FULL, r, 1);
    return r;
}

// One 8-negative batch: 8 gathers, 8 dots, merged reduce, one log_sigmoid per lane.
__device__ __forceinline__ float neg_batch8(const float* __restrict__ emb_o,
                                            const int* __restrict__ nw, int k,
                                            const float4 iv, int lane) {
    const int4 ia = *reinterpret_cast<const int4*>(nw + k);
    const int4 ib = *reinterpret_cast<const int4*>(nw + k + 4);

    float4 v0 = __ldg(reinterpret_cast<const float4*>(emb_o + (size_t)ia.x * DIM) + lane);
    float4 v1 = __ldg(reinterpret_cast<const float4*>(emb_o + (size_t)ia.y * DIM) + lane);
    float4 v2 = __ldg(reinterpret_cast<const float4*>(emb_o + (size_t)ia.z * DIM) + lane);
    float4 v3 = __ldg(reinterpret_cast<const float4*>(emb_o + (size_t)ia.w * DIM) + lane);
    float4 v4 = __ldg(reinterpret_cast<const float4*>(emb_o + (size_t)ib.x * DIM) + lane);
    float4 v5 = __ldg(reinterpret_cast<const float4*>(emb_o + (size_t)ib.y * DIM) + lane);
    float4 v6 = __ldg(reinterpret_cast<const float4*>(emb_o + (size_t)ib.z * DIM) + lane);
    float4 v7 = __ldg(reinterpret_cast<const float4*>(emb_o + (size_t)ib.w * DIM) + lane);

    float p[8];
    p[0] = dot4(iv, v0); p[1] = dot4(iv, v1);
    p[2] = dot4(iv, v2); p[3] = dot4(iv, v3);
    p[4] = dot4(iv, v4); p[5] = dot4(iv, v5);
    p[6] = dot4(iv, v6); p[7] = dot4(iv, v7);

    return log_sigmoid(-reduce8(p, lane));
}

__global__ void sgns_zero_out(float* out) { out[0] = 0.0f; }

// 2 warps per batch row: half 0 -> positives + negs [0,96); half 1 -> negs [96,200).
__global__ __launch_bounds__(256)
void sgns_kernel(const float* __restrict__ emb_i,
                 const float* __restrict__ emb_o,
                 const int*   __restrict__ iword,
                 const int*   __restrict__ owords,
                 const int*   __restrict__ nwords,
                 float*       __restrict__ out) {
    __shared__ float blk_acc;
    if (threadIdx.x == 0) blk_acc = 0.0f;
    __syncthreads();

    const int gwarp = (blockIdx.x * blockDim.x + threadIdx.x) >> 5;
    const int lane  = threadIdx.x & 31;
    const int b     = gwarp >> 1;
    const int half  = gwarp & 1;

    // Input-word vector slice for this lane (4 floats; warp covers all 128)
    const float4 iv =
        *reinterpret_cast<const float4*>(emb_i + (size_t)iword[b] * DIM + lane * 4);

    const int* __restrict__ nw = nwords + b * NNEG;

    float acc4 = 0.0f;   // per-lane; each row counted 4x across the warp
    float accU = 0.0f;   // lane-uniform; each row counted once

    if (half == 0) {
        const int* __restrict__ ow = owords + b * CTX;
        // positives: 8 batched + 2 classic
        {
            float p[8];
#pragma unroll
            for (int c = 0; c < 8; c++) {
                const float4 v = __ldg(
                    reinterpret_cast<const float4*>(emb_o + (size_t)ow[c] * DIM) + lane);
                p[c] = dot4(iv, v);
            }
            acc4 += log_sigmoid(reduce8(p, lane));
#pragma unroll
            for (int c = 8; c < CTX; c++) {
                const float4 v = __ldg(
                    reinterpret_cast<const float4*>(emb_o + (size_t)ow[c] * DIM) + lane);
                float s = dot4(iv, v);
                s += __shfl_xor_sync(FULL, s, 16);
                s += __shfl_xor_sync(FULL, s, 8);
                s += __shfl_xor_sync(FULL, s, 4);
                s += __shfl_xor_sync(FULL, s, 2);
                s += __shfl_xor_sync(FULL, s, 1);
                accU += log_sigmoid(s);
            }
        }
        // negatives [0, 96)
#pragma unroll 2
        for (int k = 0; k < 96; k += 8)
            acc4 += neg_batch8(emb_o, nw, k, iv, lane);
    } else {
        // negatives [96, 200) : 13 batches of 8
#pragma unroll 2
        for (int k = 96; k < NNEG; k += 8)
            acc4 += neg_batch8(emb_o, nw, k, iv, lane);
    }

    // Reduce acc4 across lanes (each row counted 4x) and fold in accU.
    float a = acc4;
    a += __shfl_xor_sync(FULL, a, 16);
    a += __shfl_xor_sync(FULL, a, 8);
    a += __shfl_xor_sync(FULL, a, 4);
    a += __shfl_xor_sync(FULL, a, 2);
    a += __shfl_xor_sync(FULL, a, 1);
    float total = fmaf(a, 0.25f, accU);

    // Per-block smem accumulation, then one global atomic per block.
    if (lane == 0) {
        atomicAdd(&blk_acc, -total * (1.0f / (float)(CTX * BATCH)));
    }
    __syncthreads();
    if (threadIdx.x == 0) {
        atomicAdd(out, blk_acc);
    }
}

extern "C" void kernel_launch(void* const* d_in, const int* in_sizes, int n_in,
                              void* d_out, int out_size) {
    const float* emb_i  = (const float*)d_in[0];
    const float* emb_o  = (const float*)d_in[1];
    const int*   iword  = (const int*)d_in[2];
    const int*   owords = (const int*)d_in[3];
    const int*   nwords = (const int*)d_in[4];
    float* out = (float*)d_out;

    sgns_zero_out<<<1, 1>>>(out);

    const int threads = 256;                       // 8 warps/block
    const int total_warps = BATCH * 2;             // 2 warps per batch row
    const int blocks = total_warps / (threads / 32);  // 1024
    sgns_kernel<<<blocks, threads>>>(emb_i, emb_o, iword, owords, nwords, out);
}

// round 4
// speedup vs baseline: 1.0174x; 1.0174x over previous
#include <cuda_runtime.h>
#include <cuda_fp16.h>
#include <math.h>

// Problem constants (fixed by the reference)
#define VOCAB  100000
#define DIM    128
#define BATCH  4096
#define CTX    10
#define NNEG   200   // CTX * N_NEGS
#define FULL   0xffffffffu

// fp16 scratch copy of emb_o, rebuilt every launch (25.6 MB)
__device__ __half g_emb_o_h[(size_t)VOCAB * DIM];

__device__ __forceinline__ float log_sigmoid(float x) {
    float ax = fabsf(x);
    return fminf(x, 0.0f) - __logf(1.0f + __expf(-ax));
}

// 4-half lane slice -> dot with 4-float iv slice
__device__ __forceinline__ float dot4h(const float4 iv, uint2 hv) {
    __half2 h01 = *reinterpret_cast<__half2*>(&hv.x);
    __half2 h23 = *reinterpret_cast<__half2*>(&hv.y);
    float2 f01 = __half22float2(h01);
    float2 f23 = __half22float2(h23);
    return fmaf(iv.x, f01.x, fmaf(iv.y, f01.y, fmaf(iv.z, f23.x, iv.w * f23.y)));
}

// Merge two per-lane partial-sum sets across the `bit` butterfly.
__device__ __forceinline__ float merge2(float a, float b, int lane, int bit) {
    float send = (lane & bit) ? a : b;
    float recv = __shfl_xor_sync(FULL, send, bit);
    float keep = (lane & bit) ? b : a;
    return keep + recv;
}

// Reduce 8 independent per-lane partial sums; each row's full sum lands in 4 lanes.
__device__ __forceinline__ float reduce8(const float p[8], int lane) {
    float m0 = merge2(p[0], p[1], lane, 16);
    float m1 = merge2(p[2], p[3], lane, 16);
    float m2 = merge2(p[4], p[5], lane, 16);
    float m3 = merge2(p[6], p[7], lane, 16);
    float n0 = merge2(m0, m1, lane, 8);
    float n1 = merge2(m2, m3, lane, 8);
    float r  = merge2(n0, n1, lane, 4);
    r += __shfl_xor_sync(FULL, r, 2);
    r += __shfl_xor_sync(FULL, r, 1);
    return r;
}

__global__ void sgns_zero_out(float* out) { out[0] = 0.0f; }

// fp32 -> fp16 table conversion (streaming, one float4 per thread)
__global__ __launch_bounds__(256)
void sgns_convert(const float4* __restrict__ src) {
    const int n4 = VOCAB * DIM / 4;  // 3,200,000
    int i = blockIdx.x * blockDim.x + threadIdx.x;
    if (i < n4) {
        float4 v = __ldg(src + i);
        __half2 a = __floats2half2_rn(v.x, v.y);
        __half2 b = __floats2half2_rn(v.z, v.w);
        uint2 o;
        o.x = *reinterpret_cast<unsigned*>(&a);
        o.y = *reinterpret_cast<unsigned*>(&b);
        reinterpret_cast<uint2*>(g_emb_o_h)[i] = o;
    }
}

__device__ __forceinline__ const uint2* row_h(int idx) {
    return reinterpret_cast<const uint2*>(g_emb_o_h) + (size_t)idx * (DIM / 4);
}

__global__ __launch_bounds__(256)
void sgns_kernel(const float* __restrict__ emb_i,
                 const int*   __restrict__ iword,
                 const int*   __restrict__ owords,
                 const int*   __restrict__ nwords,
                 float*       __restrict__ out) {
    const int warp = (blockIdx.x * blockDim.x + threadIdx.x) >> 5;
    const int lane = threadIdx.x & 31;
    if (warp >= BATCH) return;

    const float4 iv =
        *reinterpret_cast<const float4*>(emb_i + (size_t)iword[warp] * DIM + lane * 4);

    const int* __restrict__ ow = owords + warp * CTX;
    const int* __restrict__ nw = nwords + warp * NNEG;

    float acc4 = 0.0f;   // per-lane; each row counted 4x across the warp
    float accU = 0.0f;   // lane-uniform; each row counted once

    // ---- positives: 8 batched + 2 classic ----
    {
        float p[8];
#pragma unroll
        for (int c = 0; c < 8; c++) {
            uint2 hv = __ldg(row_h(ow[c]) + lane);
            p[c] = dot4h(iv, hv);
        }
        acc4 += log_sigmoid(reduce8(p, lane));

#pragma unroll
        for (int c = 8; c < CTX; c++) {
            uint2 hv = __ldg(row_h(ow[c]) + lane);
            float s = dot4h(iv, hv);
            s += __shfl_xor_sync(FULL, s, 16);
            s += __shfl_xor_sync(FULL, s, 8);
            s += __shfl_xor_sync(FULL, s, 4);
            s += __shfl_xor_sync(FULL, s, 2);
            s += __shfl_xor_sync(FULL, s, 1);
            accU += log_sigmoid(s);
        }
    }

    // ---- negatives: 200 rows = 25 batches of 8 ----
    for (int k = 0; k < NNEG; k += 8) {
        const int4 ia = *reinterpret_cast<const int4*>(nw + k);
        const int4 ib = *reinterpret_cast<const int4*>(nw + k + 4);

        uint2 v0 = __ldg(row_h(ia.x) + lane);
        uint2 v1 = __ldg(row_h(ia.y) + lane);
        uint2 v2 = __ldg(row_h(ia.z) + lane);
        uint2 v3 = __ldg(row_h(ia.w) + lane);
        uint2 v4 = __ldg(row_h(ib.x) + lane);
        uint2 v5 = __ldg(row_h(ib.y) + lane);
        uint2 v6 = __ldg(row_h(ib.z) + lane);
        uint2 v7 = __ldg(row_h(ib.w) + lane);

        float p[8];
        p[0] = dot4h(iv, v0); p[1] = dot4h(iv, v1);
        p[2] = dot4h(iv, v2); p[3] = dot4h(iv, v3);
        p[4] = dot4h(iv, v4); p[5] = dot4h(iv, v5);
        p[6] = dot4h(iv, v6); p[7] = dot4h(iv, v7);

        acc4 += log_sigmoid(-reduce8(p, lane));
    }

    // Reduce acc4 across lanes (each row counted 4x) and fold in accU.
    float a = acc4;
    a += __shfl_xor_sync(FULL, a, 16);
    a += __shfl_xor_sync(FULL, a, 8);
    a += __shfl_xor_sync(FULL, a, 4);
    a += __shfl_xor_sync(FULL, a, 2);
    a += __shfl_xor_sync(FULL, a, 1);
    float total = fmaf(a, 0.25f, accU);

    if (lane == 0) {
        atomicAdd(out, -total * (1.0f / (float)(CTX * BATCH)));
    }
}

extern "C" void kernel_launch(void* const* d_in, const int* in_sizes, int n_in,
                              void* d_out, int out_size) {
    const float* emb_i  = (const float*)d_in[0];
    const float* emb_o  = (const float*)d_in[1];
    const int*   iword  = (const int*)d_in[2];
    const int*   owords = (const int*)d_in[3];
    const int*   nwords = (const int*)d_in[4];
    float* out = (float*)d_out;

    sgns_zero_out<<<1, 1>>>(out);

    // Convert emb_o to fp16 scratch table
    const int n4 = VOCAB * DIM / 4;
    sgns_convert<<<(n4 + 255) / 256, 256>>>(reinterpret_cast<const float4*>(emb_o));

    // Main: 1 warp per batch row
    const int threads = 256;
    const int blocks = (BATCH + (threads / 32) - 1) / (threads / 32);
    sgns_kernel<<<blocks, threads>>>(emb_i, iword, owords, nwords, out);
}